// round 1
// baseline (speedup 1.0000x reference)
#include <cuda_runtime.h>
#include <math_constants.h>
#include <cstdint>
#include <cstddef>

static constexpr int Vv = 16000, Cc = 4096, Hh = 256, SPW = 32, Nn = 32, Tt = 128, Tm1 = 127;

// ---------------- scratch layout (single __device__ arena; no runtime allocs) ----
constexpr size_t SZ_MAT   = (size_t)Cc * Hh;                  // 1,048,576
constexpr size_t OFF_H    = 0;
constexpr size_t OFF_RS   = OFF_H    + SZ_MAT;
constexpr size_t OFF_RST  = OFF_RS   + SZ_MAT;
constexpr size_t OFF_RP   = OFF_RST  + SZ_MAT;
constexpr size_t OFF_TRANS= OFF_RP   + SZ_MAT;                // 4096x4096
constexpr size_t OFF_TLSE = OFF_TRANS+ (size_t)Cc * Cc;
constexpr size_t OFF_SLOG = OFF_TLSE + Cc;
constexpr size_t OFF_SLSE = OFF_SLOG + Cc;
constexpr size_t OFF_EWT  = OFF_SLSE + 32;                    // V x H transpose of e_out_w
constexpr size_t OFF_L    = OFF_EWT  + (size_t)Vv * Hh;       // V x SPW sparse em logits
constexpr size_t OFF_RMF  = OFF_L    + (size_t)Vv * SPW;
constexpr size_t OFF_RSUM = OFF_RMF  + Cc;
constexpr size_t OFF_STLSE= OFF_RSUM + Cc;
constexpr size_t OFF_OBS  = OFF_STLSE+ Cc;                    // N*T*SPW
constexpr size_t OFF_INIT = OFF_OBS  + (size_t)Nn * Tt * SPW; // N*SPW
constexpr size_t OFF_PHI  = OFF_INIT + (size_t)Nn * SPW;      // Tm1*N*32*32
constexpr size_t OFF_AP   = OFF_PHI  + (size_t)Tm1 * Nn * SPW * SPW;
constexpr size_t OFF_BN   = OFF_AP   + (size_t)Tm1 * Nn * SPW;
constexpr size_t OFF_LOGZ = OFF_BN   + (size_t)Tm1 * Nn * SPW;
constexpr size_t SCRATCH_TOTAL = OFF_LOGZ + 64;

__device__ float g_scr[SCRATCH_TOTAL];
__device__ int   g_rowmax[Cc];

// ---------------- helpers ----------------
__device__ __forceinline__ int ford(float f) {
    int i = __float_as_int(f);
    return i >= 0 ? i : (i ^ 0x7fffffff);
}
__device__ __forceinline__ float deord(int i) {
    return __int_as_float(i >= 0 ? i : (i ^ 0x7fffffff));
}
__device__ __forceinline__ void lse_acc(float& m, float& s, float v) {
    if (v > m) { s = s * __expf(m - v) + 1.f; m = v; }
    else       { s += __expf(v - m); }
}
__device__ __forceinline__ void lse_merge(float& m, float& s, float m2, float s2) {
    if (m2 > m) { s = s * __expf(m - m2) + s2; m = m2; }
    else        { s += s2 * __expf(m2 - m); }
}
__device__ __forceinline__ float warp_sum(float v) {
#pragma unroll
    for (int o = 16; o > 0; o >>= 1) v += __shfl_xor_sync(0xffffffffu, v, o);
    return v;
}
__device__ __forceinline__ float warp_max(float v) {
#pragma unroll
    for (int o = 16; o > 0; o >>= 1) v = fmaxf(v, __shfl_xor_sync(0xffffffffu, v, o));
    return v;
}

// ---------------- GEMM: C = A @ B (or A @ B^T), optional relu+bias / +residual ----
// EPI: 0 = none, 1 = relu(x + bias[col]), 2 = relu(x + bias[col]) + R[row,col]
template <int EPI, bool TRB>
__global__ __launch_bounds__(256) void gemm_k(
    const float* __restrict__ A, const float* __restrict__ B,
    const float* __restrict__ bias, const float* __restrict__ R,
    float* __restrict__ Co, int M, int N, int K)
{
    constexpr int BM = 128, BN = 128, BK = 16;
    __shared__ float As[BK][BM];
    __shared__ float Bs[BK][BN];
    int tid = threadIdx.x;
    int bm = blockIdx.y * BM, bn = blockIdx.x * BN;
    int tx = tid & 15, ty = tid >> 4;
    float acc[8][8] = {};
    for (int k0 = 0; k0 < K; k0 += BK) {
#pragma unroll
        for (int i = 0; i < 2; i++) {
            int f = tid + i * 256;                     // 512 float4 = 128x16 A tile
            int r = f >> 2, c4 = (f & 3) * 4;
            float4 v = *(const float4*)&A[(size_t)(bm + r) * K + k0 + c4];
            As[c4 + 0][r] = v.x; As[c4 + 1][r] = v.y; As[c4 + 2][r] = v.z; As[c4 + 3][r] = v.w;
        }
        if (TRB) {
#pragma unroll
            for (int i = 0; i < 2; i++) {
                int f = tid + i * 256;
                int r = f >> 2, c4 = (f & 3) * 4;
                float4 v = *(const float4*)&B[(size_t)(bn + r) * K + k0 + c4];
                Bs[c4 + 0][r] = v.x; Bs[c4 + 1][r] = v.y; Bs[c4 + 2][r] = v.z; Bs[c4 + 3][r] = v.w;
            }
        } else {
#pragma unroll
            for (int i = 0; i < 2; i++) {
                int f = tid + i * 256;                 // 16 rows x 32 float4
                int r = f >> 5, c = (f & 31) * 4;
                *(float4*)&Bs[r][c] = *(const float4*)&B[(size_t)(k0 + r) * N + bn + c];
            }
        }
        __syncthreads();
#pragma unroll
        for (int k = 0; k < BK; k++) {
            float a[8], b[8];
            *(float4*)&a[0] = *(float4*)&As[k][ty * 8];
            *(float4*)&a[4] = *(float4*)&As[k][ty * 8 + 4];
            *(float4*)&b[0] = *(float4*)&Bs[k][tx * 8];
            *(float4*)&b[4] = *(float4*)&Bs[k][tx * 8 + 4];
#pragma unroll
            for (int i = 0; i < 8; i++)
#pragma unroll
                for (int j = 0; j < 8; j++) acc[i][j] += a[i] * b[j];
        }
        __syncthreads();
    }
#pragma unroll
    for (int i = 0; i < 8; i++) {
        int row = bm + ty * 8 + i;
#pragma unroll
        for (int j = 0; j < 8; j++) {
            int col = bn + tx * 8 + j;
            float v = acc[i][j];
            if (EPI >= 1) v = fmaxf(v + bias[col], 0.f);
            if (EPI == 2) v += R[(size_t)row * N + col];
            Co[(size_t)row * N + col] = v;
        }
    }
}

// ---------------- start head: per-row dot with s_out_w ----------------
__global__ void slog_k(const float* __restrict__ Rr, const float* __restrict__ w,
                       const float* __restrict__ b, float* __restrict__ slog) {
    int row  = blockIdx.x * 8 + (threadIdx.x >> 5);
    int lane = threadIdx.x & 31;
    const float* r = Rr + (size_t)row * Hh;
    float p = 0.f;
#pragma unroll
    for (int q = 0; q < 8; q++) p += r[lane + 32 * q] * w[lane + 32 * q];
    p = warp_sum(p);
    if (lane == 0) slog[row] = p + b[0];
}

// lse over 4096 values, single block
__global__ __launch_bounds__(1024) void lse4096_k(const float* __restrict__ x, float* __restrict__ out) {
    int tid = threadIdx.x;
    float m = -CUDART_INF_F, s = 0.f;
    for (int i = tid; i < Cc; i += 1024) lse_acc(m, s, x[i]);
#pragma unroll
    for (int o = 16; o > 0; o >>= 1) {
        float m2 = __shfl_xor_sync(0xffffffffu, m, o);
        float s2 = __shfl_xor_sync(0xffffffffu, s, o);
        lse_merge(m, s, m2, s2);
    }
    __shared__ float sm[32], ss[32];
    int w = tid >> 5, lane = tid & 31;
    if (lane == 0) { sm[w] = m; ss[w] = s; }
    __syncthreads();
    if (tid == 0) {
        float M = sm[0], S = ss[0];
        for (int i = 1; i < 32; i++) lse_merge(M, S, sm[i], ss[i]);
        out[0] = M + __logf(S);
    }
}

// per-row lse of trans logits (block per row, 256 threads)
__global__ void translse_k(const float* __restrict__ X, float* __restrict__ out) {
    const float* x = X + (size_t)blockIdx.x * Cc;
    int tid = threadIdx.x;
    float m = -CUDART_INF_F, s = 0.f;
    for (int i = tid; i < Cc; i += 256) lse_acc(m, s, x[i]);
#pragma unroll
    for (int o = 16; o > 0; o >>= 1) {
        float m2 = __shfl_xor_sync(0xffffffffu, m, o);
        float s2 = __shfl_xor_sync(0xffffffffu, s, o);
        lse_merge(m, s, m2, s2);
    }
    __shared__ float sm[8], ss[8];
    int w = tid >> 5, lane = tid & 31;
    if (lane == 0) { sm[w] = m; ss[w] = s; }
    __syncthreads();
    if (tid == 0) {
        float M = sm[0], S = ss[0];
        for (int i = 1; i < 8; i++) lse_merge(M, S, sm[i], ss[i]);
        out[blockIdx.x] = M + __logf(S);
    }
}

// transpose e_out_w (H x V) -> (V x H)
__global__ void transpose_k(const float* __restrict__ in, float* __restrict__ out) {
    __shared__ float t[32][33];
    int bx = blockIdx.x * 32;  // V dim
    int by = blockIdx.y * 32;  // H dim
    int x = threadIdx.x, y = threadIdx.y;
#pragma unroll
    for (int i = 0; i < 32; i += 8)
        t[y + i][x] = in[(size_t)(by + y + i) * Vv + bx + x];
    __syncthreads();
#pragma unroll
    for (int i = 0; i < 32; i += 8)
        out[(size_t)(bx + y + i) * Hh + by + x] = t[x][y + i];
}

__global__ void initmax_k(int* __restrict__ rm, float* __restrict__ rs) {
    int i = blockIdx.x * 256 + threadIdx.x;
    if (i < Cc) { rm[i] = (int)0x80000000; rs[i] = 0.f; }
}

// sparse emission logits: block per word v
__global__ __launch_bounds__(256) void emlog_k(
    const float* __restrict__ pre, const float* __restrict__ ewT,
    const float* __restrict__ eb, const int* __restrict__ w2s,
    float* __restrict__ L, int* __restrict__ rowmax)
{
    int v = blockIdx.x;
    __shared__ float ecol[Hh];
    __shared__ int st[SPW];
    int tid = threadIdx.x;
    ecol[tid] = ewT[(size_t)v * Hh + tid];
    if (tid < SPW) st[tid] = w2s[v * SPW + tid];
    __syncthreads();
    int w = tid >> 5, lane = tid & 31;
    float bv = eb[v];
    for (int jj = w; jj < SPW; jj += 8) {
        int c = st[jj];
        const float* pr = pre + (size_t)c * Hh;
        float p = 0.f;
#pragma unroll
        for (int q = 0; q < 8; q++) p += pr[lane + 32 * q] * ecol[lane + 32 * q];
        p = warp_sum(p);
        if (lane == 0) {
            float val = p + bv;
            L[v * SPW + jj] = val;
            atomicMax(&rowmax[c], ford(val));
        }
    }
}

__global__ void rmdec_k(const int* __restrict__ rm, float* __restrict__ rmf) {
    int i = blockIdx.x * 256 + threadIdx.x;
    if (i < Cc) rmf[i] = deord(rm[i]);
}

// per-state exp sum, dedup within each word's state list (mask semantics)
__global__ void emsum_k(const int* __restrict__ w2s, const float* __restrict__ L,
                        const float* __restrict__ rmf, float* __restrict__ rsum) {
    int gid = blockIdx.x * 256 + threadIdx.x;
    int v = gid >> 5, j = gid & 31;
    int c = w2s[v * SPW + j];
    for (int jp = 0; jp < j; jp++)
        if (w2s[v * SPW + jp] == c) return;  // duplicate -> counted once in mask
    atomicAdd(&rsum[c], __expf(L[gid] - rmf[c]));
}

__global__ void stlse_k(const float* __restrict__ rmf, const float* __restrict__ rsum,
                        float* __restrict__ stlse) {
    int i = blockIdx.x * 256 + threadIdx.x;
    if (i < Cc) stlse[i] = rmf[i] + __logf(rsum[i]);
}

// obs[n,t,j] and init[n,j]
__global__ void obs_k(const int* __restrict__ text, const int* __restrict__ w2s,
                      const float* __restrict__ L, const float* __restrict__ stlse,
                      const float* __restrict__ slog, const float* __restrict__ slse,
                      float* __restrict__ obs, float* __restrict__ initb) {
    int gid = blockIdx.x * 256 + threadIdx.x;   // N*T*SPW threads
    int tok = gid >> 5, j = gid & 31;
    int v = text[tok];
    int c = w2s[v * SPW + j];
    obs[gid] = L[v * SPW + j] - stlse[c];
    if ((tok & (Tt - 1)) == 0)
        initb[(tok >> 7) * SPW + j] = slog[c] - slse[0];
}

// phiT[t,n,k,j] = trans[c_t[j], c_{t+1}[k]] - tlse[c_t[j]] + obs[n,t+1,k] + (t==0)(init[n,j]+obs[n,0,j])
__global__ __launch_bounds__(1024) void phi_k(
    const int* __restrict__ text, const int* __restrict__ w2s,
    const float* __restrict__ trans, const float* __restrict__ tlse,
    const float* __restrict__ obs, const float* __restrict__ initb,
    float* __restrict__ phi)
{
    int b = blockIdx.x;                 // Nn*Tm1 blocks
    int n = b / Tm1, t = b % Tm1;
    __shared__ int c0[SPW], c1[SPW];
    __shared__ float ob1[SPW], iob[SPW];
    int tid = threadIdx.x;
    if (tid < SPW) {
        int v0 = text[n * Tt + t], v1 = text[n * Tt + t + 1];
        c0[tid] = w2s[v0 * SPW + tid];
        c1[tid] = w2s[v1 * SPW + tid];
        ob1[tid] = obs[(size_t)(n * Tt + t + 1) * SPW + tid];
        iob[tid] = (t == 0) ? (initb[n * SPW + tid] + obs[(size_t)(n * Tt) * SPW + tid]) : 0.f;
    }
    __syncthreads();
    int k = tid >> 5, j = tid & 31;
    float val = trans[(size_t)c0[j] * Cc + c1[k]] - tlse[c0[j]] + ob1[k] + iob[j];
    phi[(size_t)(t * Nn + n) * 1024 + tid] = val;
}

// forward (blocks 0..31) and backward (blocks 32..63) scans
__global__ __launch_bounds__(1024) void scan_k(
    const float* __restrict__ phi, float* __restrict__ ap, float* __restrict__ bn,
    float* __restrict__ logZ, float* __restrict__ out)
{
    __shared__ float a_s[SPW];
    __shared__ float tile[SPW * 33];
    int tid = threadIdx.x, w = tid >> 5, lane = tid & 31;
    bool bwd = blockIdx.x >= Nn;
    int n = bwd ? (int)blockIdx.x - Nn : (int)blockIdx.x;
    if (tid < SPW) a_s[tid] = 0.f;
    __syncthreads();
    if (!bwd) {
        float pv = phi[(size_t)n * 1024 + tid];
        for (int t = 0; t < Tm1; t++) {
            float pvn = (t + 1 < Tm1) ? phi[(size_t)((t + 1) * Nn + n) * 1024 + tid] : 0.f;
            if (tid < SPW) ap[(size_t)(t * Nn + n) * SPW + tid] = a_s[tid];
            float x = pv + a_s[lane];                  // lane = j, warp = k
            float m = warp_max(x);
            float s = warp_sum(__expf(x - m));
            float nv = m + __logf(s);
            __syncthreads();
            if (lane == 0) a_s[w] = nv;
            __syncthreads();
            pv = pvn;
        }
        if (w == 0) {
            float x = a_s[lane];
            float m = warp_max(x);
            float s = warp_sum(__expf(x - m));
            float lz = m + __logf(s);
            if (lane == 0) logZ[n] = lz;
            out[2 + n * SPW + lane] = x - lz;          // log_softmax(alpha_T)
        }
    } else {
        float pv = phi[(size_t)((Tm1 - 1) * Nn + n) * 1024 + tid];
        for (int t = Tm1 - 1; t >= 0; t--) {
            float pvn = (t > 0) ? phi[(size_t)((t - 1) * Nn + n) * 1024 + tid] : 0.f;
            tile[w * 33 + lane] = pv;                  // tile[k][j]
            if (tid < SPW) bn[(size_t)(t * Nn + n) * SPW + tid] = a_s[tid];
            __syncthreads();
            float x = tile[lane * 33 + w] + a_s[lane]; // thread (j=w, k=lane)
            float m = warp_max(x);
            float s = warp_sum(__expf(x - m));
            float nv = m + __logf(s);
            __syncthreads();
            if (lane == 0) a_s[w] = nv;
            __syncthreads();
            pv = pvn;
        }
    }
}

__global__ void evid_k(const float* __restrict__ logZ, float* __restrict__ out) {
    if (threadIdx.x == 0) {
        float s = 0.f;
        for (int i = 0; i < Nn; i++) s += logZ[i];
        out[1] = s;
        out[0] = 0.f;   // zero elbo accumulator
    }
}

__global__ __launch_bounds__(1024) void elbo_k(
    const float* __restrict__ phi, const float* __restrict__ ap,
    const float* __restrict__ bn, const float* __restrict__ logZ,
    float* __restrict__ out)
{
    int e = blockIdx.x;                 // e = t*Nn + n
    int n = e % Nn;
    __shared__ float sap[SPW], sbn[SPW], ws[32];
    int tid = threadIdx.x;
    if (tid < SPW) { sap[tid] = ap[(size_t)e * SPW + tid]; sbn[tid] = bn[(size_t)e * SPW + tid]; }
    __syncthreads();
    int k = tid >> 5, j = tid & 31;
    float p = phi[(size_t)e * 1024 + tid];
    float term = __expf(sap[j] + p + sbn[k] - logZ[n]) * p;
    term = warp_sum(term);
    if (j == 0) ws[k] = term;
    __syncthreads();
    if (tid < 32) {
        float v = warp_sum(ws[tid]);
        if (tid == 0) atomicAdd(&out[0], v);
    }
}

// ---------------- launcher ----------------
extern "C" void kernel_launch(void* const* d_in, const int* in_sizes, int n_in,
                              void* d_out, int out_size) {
    const float* start_emb = (const float*)d_in[0];
    const float* sw1  = (const float*)d_in[1];
    const float* sb1  = (const float*)d_in[2];
    const float* sw2  = (const float*)d_in[3];
    const float* sb2  = (const float*)d_in[4];
    const float* s_out_w = (const float*)d_in[5];
    const float* s_out_b = (const float*)d_in[6];
    const float* state_emb = (const float*)d_in[7];
    const float* tw1  = (const float*)d_in[8];
    const float* tb1  = (const float*)d_in[9];
    const float* tw2  = (const float*)d_in[10];
    const float* tb2  = (const float*)d_in[11];
    const float* nsp  = (const float*)d_in[12];
    const float* pre_emb = (const float*)d_in[13];
    const float* ew1  = (const float*)d_in[14];
    const float* eb1  = (const float*)d_in[15];
    const float* ew2  = (const float*)d_in[16];
    const float* eb2  = (const float*)d_in[17];
    const float* e_out_w = (const float*)d_in[18];
    const float* e_out_b = (const float*)d_in[19];
    const int* text = (const int*)d_in[20];
    const int* w2s  = (const int*)d_in[21];
    float* out = (float*)d_out;

    float* S = nullptr; int* RM = nullptr;
    cudaGetSymbolAddress((void**)&S, g_scr);
    cudaGetSymbolAddress((void**)&RM, g_rowmax);

    dim3 gMLP(Hh / 128, Cc / 128);   // (2, 32)
    dim3 gTR(Cc / 128, Cc / 128);    // (32, 32)

    initmax_k<<<16, 256>>>(RM, S + OFF_RSUM);

    // residual MLPs (fp32 SIMT GEMMs)
    gemm_k<1, false><<<gMLP, 256>>>(start_emb, sw1, sb1, nullptr, S + OFF_H, Cc, Hh, Hh);
    gemm_k<2, false><<<gMLP, 256>>>(S + OFF_H, sw2, sb2, start_emb, S + OFF_RS, Cc, Hh, Hh);
    gemm_k<1, false><<<gMLP, 256>>>(state_emb, tw1, tb1, nullptr, S + OFF_H, Cc, Hh, Hh);
    gemm_k<2, false><<<gMLP, 256>>>(S + OFF_H, tw2, tb2, state_emb, S + OFF_RST, Cc, Hh, Hh);
    gemm_k<1, false><<<gMLP, 256>>>(pre_emb, ew1, eb1, nullptr, S + OFF_H, Cc, Hh, Hh);
    gemm_k<2, false><<<gMLP, 256>>>(S + OFF_H, ew2, eb2, pre_emb, S + OFF_RP, Cc, Hh, Hh);

    // start distribution
    slog_k<<<Cc / 8, 256>>>(S + OFF_RS, s_out_w, s_out_b, S + OFF_SLOG);
    lse4096_k<<<1, 1024>>>(S + OFF_SLOG, S + OFF_SLSE);

    // transition logits + row lse (double log_softmax ~ single; second is identity)
    gemm_k<0, true><<<gTR, 256>>>(S + OFF_RST, nsp, nullptr, nullptr, S + OFF_TRANS, Cc, Cc, Hh);
    translse_k<<<Cc, 256>>>(S + OFF_TRANS, S + OFF_TLSE);

    // sparse emission
    transpose_k<<<dim3(Vv / 32, Hh / 32), dim3(32, 8)>>>(e_out_w, S + OFF_EWT);
    emlog_k<<<Vv, 256>>>(S + OFF_RP, S + OFF_EWT, e_out_b, w2s, S + OFF_L, RM);
    rmdec_k<<<16, 256>>>(RM, S + OFF_RMF);
    emsum_k<<<Vv * SPW / 256, 256>>>(w2s, S + OFF_L, S + OFF_RMF, S + OFF_RSUM);
    stlse_k<<<16, 256>>>(S + OFF_RMF, S + OFF_RSUM, S + OFF_STLSE);

    // obs/init, phi tensor, scans, reductions
    obs_k<<<Nn * Tt * SPW / 256, 256>>>(text, w2s, S + OFF_L, S + OFF_STLSE,
                                        S + OFF_SLOG, S + OFF_SLSE, S + OFF_OBS, S + OFF_INIT);
    phi_k<<<Nn * Tm1, 1024>>>(text, w2s, S + OFF_TRANS, S + OFF_TLSE,
                              S + OFF_OBS, S + OFF_INIT, S + OFF_PHI);
    scan_k<<<2 * Nn, 1024>>>(S + OFF_PHI, S + OFF_AP, S + OFF_BN, S + OFF_LOGZ, out);
    evid_k<<<1, 32>>>(S + OFF_LOGZ, out);
    elbo_k<<<Tm1 * Nn, 1024>>>(S + OFF_PHI, S + OFF_AP, S + OFF_BN, S + OFF_LOGZ, out);
}

// round 2
// speedup vs baseline: 1.2665x; 1.2665x over previous
#include <cuda_runtime.h>
#include <math_constants.h>
#include <cstdint>
#include <cstddef>

static constexpr int Vv = 16000, Cc = 4096, Hh = 256, SPW = 32, Nn = 32, Tt = 128, Tm1 = 127;

// ---------------- scratch layout ----------------
constexpr size_t SZ_MAT   = (size_t)Cc * Hh;
constexpr size_t OFF_H0   = 0;
constexpr size_t OFF_H1   = OFF_H0   + SZ_MAT;
constexpr size_t OFF_H2   = OFF_H1   + SZ_MAT;
constexpr size_t OFF_RS   = OFF_H2   + SZ_MAT;
constexpr size_t OFF_RST  = OFF_RS   + SZ_MAT;
constexpr size_t OFF_RP   = OFF_RST  + SZ_MAT;
constexpr size_t OFF_TRANS= OFF_RP   + SZ_MAT;                // 4096x4096
constexpr size_t OFF_TLSE = OFF_TRANS+ (size_t)Cc * Cc;
constexpr size_t OFF_SLOG = OFF_TLSE + Cc;
constexpr size_t OFF_SLSE = OFF_SLOG + Cc;
constexpr size_t OFF_EWT  = OFF_SLSE + 32;                    // V x H
constexpr size_t OFF_L    = OFF_EWT  + (size_t)Vv * Hh;       // V x SPW
constexpr size_t OFF_RMF  = OFF_L    + (size_t)Vv * SPW;
constexpr size_t OFF_RSUM = OFF_RMF  + Cc;
constexpr size_t OFF_STLSE= OFF_RSUM + Cc;
constexpr size_t OFF_OBS  = OFF_STLSE+ Cc;
constexpr size_t OFF_INIT = OFF_OBS  + (size_t)Nn * Tt * SPW;
constexpr size_t OFF_PHI  = OFF_INIT + (size_t)Nn * SPW;
constexpr size_t OFF_AP   = OFF_PHI  + (size_t)Tm1 * Nn * SPW * SPW;
constexpr size_t OFF_BN   = OFF_AP   + (size_t)Tm1 * Nn * SPW;
constexpr size_t OFF_LOGZ = OFF_BN   + (size_t)Tm1 * Nn * SPW;
constexpr size_t SCRATCH_TOTAL = OFF_LOGZ + 64;

__device__ float g_scr[SCRATCH_TOTAL];
__device__ int   g_rowmax[Cc];

// ---------------- helpers ----------------
__device__ __forceinline__ int ford(float f) {
    int i = __float_as_int(f);
    return i >= 0 ? i : (i ^ 0x7fffffff);
}
__device__ __forceinline__ float deord(int i) {
    return __int_as_float(i >= 0 ? i : (i ^ 0x7fffffff));
}
__device__ __forceinline__ void lse_acc(float& m, float& s, float v) {
    if (v > m) { s = s * __expf(m - v) + 1.f; m = v; }
    else       { s += __expf(v - m); }
}
__device__ __forceinline__ void lse_merge(float& m, float& s, float m2, float s2) {
    if (m2 > m) { s = s * __expf(m - m2) + s2; m = m2; }
    else        { s += s2 * __expf(m2 - m); }
}
__device__ __forceinline__ float warp_sum(float v) {
#pragma unroll
    for (int o = 16; o > 0; o >>= 1) v += __shfl_xor_sync(0xffffffffu, v, o);
    return v;
}
__device__ __forceinline__ float warp_max(float v) {
#pragma unroll
    for (int o = 16; o > 0; o >>= 1) v = fmaxf(v, __shfl_xor_sync(0xffffffffu, v, o));
    return v;
}

// ---------------- tf32 tensor-core GEMM (3xTF32 for fp32 accuracy) ----------------
__device__ __forceinline__ uint32_t f2tf(float x) {
    uint32_t r;
    asm("cvt.rna.tf32.f32 %0, %1;" : "=r"(r) : "f"(x));
    return r;
}
__device__ __forceinline__ void tf_split(float x, uint32_t& hi, uint32_t& lo) {
    hi = f2tf(x);
    lo = f2tf(x - __uint_as_float(hi));
}
__device__ __forceinline__ void mma_tf32(float4& d, const uint32_t* a, const uint32_t* b) {
    asm volatile(
        "mma.sync.aligned.m16n8k8.row.col.f32.tf32.tf32.f32 "
        "{%0,%1,%2,%3}, {%4,%5,%6,%7}, {%8,%9}, {%0,%1,%2,%3};"
        : "+f"(d.x), "+f"(d.y), "+f"(d.z), "+f"(d.w)
        : "r"(a[0]), "r"(a[1]), "r"(a[2]), "r"(a[3]), "r"(b[0]), "r"(b[1]));
}

struct P3 { const float* A; const float* B; const float* bias; const float* R; float* C; };
struct Batch { P3 p[3]; };

// C = A(MxK) @ B, B either KxN (TRB=0) or NxK row-major = B^T (TRB=1).
// EPI: 0 none, 1 relu(x+bias), 2 relu(x+bias)+R
template <int EPI, bool TRB>
__global__ __launch_bounds__(256, 2) void gemm_tc(Batch bt, int M, int N, int K) {
    constexpr int BM = 128, BN = 64, BK = 16;
    __shared__ uint32_t Ah[BK][BM + 8], Al[BK][BM + 8];
    __shared__ uint32_t Bh[BK][BN + 8], Bl[BK][BN + 8];
    const P3 pp = bt.p[blockIdx.z];
    int tid = threadIdx.x;
    int bm = blockIdx.y * BM, bn = blockIdx.x * BN;
    int wid = tid >> 5, lane = tid & 31;
    int gid = lane >> 2, tg = lane & 3;
    int warp_m = (wid & 3) * 32, warp_n = (wid >> 2) * 32;

    float4 acc[2][4];
#pragma unroll
    for (int i = 0; i < 2; i++)
#pragma unroll
        for (int j = 0; j < 4; j++) acc[i][j] = make_float4(0.f, 0.f, 0.f, 0.f);

    for (int k0 = 0; k0 < K; k0 += BK) {
        // A tile: 128 x 16
#pragma unroll
        for (int i = 0; i < 2; i++) {
            int f = tid + i * 256;
            int r = f >> 2, c4 = (f & 3) * 4;
            float4 v = *(const float4*)&pp.A[(size_t)(bm + r) * K + k0 + c4];
            tf_split(v.x, Ah[c4 + 0][r], Al[c4 + 0][r]);
            tf_split(v.y, Ah[c4 + 1][r], Al[c4 + 1][r]);
            tf_split(v.z, Ah[c4 + 2][r], Al[c4 + 2][r]);
            tf_split(v.w, Ah[c4 + 3][r], Al[c4 + 3][r]);
        }
        // B tile: want Bs[k][n]
        if (TRB) {
            int r = tid >> 2, c4 = (tid & 3) * 4;      // r = n, c4 = k
            float4 v = *(const float4*)&pp.B[(size_t)(bn + r) * K + k0 + c4];
            tf_split(v.x, Bh[c4 + 0][r], Bl[c4 + 0][r]);
            tf_split(v.y, Bh[c4 + 1][r], Bl[c4 + 1][r]);
            tf_split(v.z, Bh[c4 + 2][r], Bl[c4 + 2][r]);
            tf_split(v.w, Bh[c4 + 3][r], Bl[c4 + 3][r]);
        } else {
            int r = tid >> 4, c = (tid & 15) * 4;      // r = k, c = n
            float4 v = *(const float4*)&pp.B[(size_t)(k0 + r) * N + bn + c];
            tf_split(v.x, Bh[r][c + 0], Bl[r][c + 0]);
            tf_split(v.y, Bh[r][c + 1], Bl[r][c + 1]);
            tf_split(v.z, Bh[r][c + 2], Bl[r][c + 2]);
            tf_split(v.w, Bh[r][c + 3], Bl[r][c + 3]);
        }
        __syncthreads();
#pragma unroll
        for (int kk = 0; kk < BK; kk += 8) {
            uint32_t ah[2][4], al[2][4], bh[4][2], bl[4][2];
#pragma unroll
            for (int mt = 0; mt < 2; mt++) {
                int rb = warp_m + mt * 16 + gid;
                ah[mt][0] = Ah[kk + tg][rb];     al[mt][0] = Al[kk + tg][rb];
                ah[mt][1] = Ah[kk + tg][rb + 8]; al[mt][1] = Al[kk + tg][rb + 8];
                ah[mt][2] = Ah[kk + tg + 4][rb];     al[mt][2] = Al[kk + tg + 4][rb];
                ah[mt][3] = Ah[kk + tg + 4][rb + 8]; al[mt][3] = Al[kk + tg + 4][rb + 8];
            }
#pragma unroll
            for (int nt = 0; nt < 4; nt++) {
                int cb = warp_n + nt * 8 + gid;
                bh[nt][0] = Bh[kk + tg][cb];     bl[nt][0] = Bl[kk + tg][cb];
                bh[nt][1] = Bh[kk + tg + 4][cb]; bl[nt][1] = Bl[kk + tg + 4][cb];
            }
#pragma unroll
            for (int mt = 0; mt < 2; mt++)
#pragma unroll
                for (int nt = 0; nt < 4; nt++) {
                    mma_tf32(acc[mt][nt], ah[mt], bh[nt]);
                    mma_tf32(acc[mt][nt], al[mt], bh[nt]);
                    mma_tf32(acc[mt][nt], ah[mt], bl[nt]);
                }
        }
        __syncthreads();
    }

    // epilogue
#pragma unroll
    for (int mt = 0; mt < 2; mt++) {
        int row0 = bm + warp_m + mt * 16 + gid;
#pragma unroll
        for (int nt = 0; nt < 4; nt++) {
            int col = bn + warp_n + nt * 8 + 2 * tg;
            float4 v = acc[mt][nt];
            if (EPI >= 1) {
                float b0 = pp.bias[col], b1 = pp.bias[col + 1];
                v.x = fmaxf(v.x + b0, 0.f); v.y = fmaxf(v.y + b1, 0.f);
                v.z = fmaxf(v.z + b0, 0.f); v.w = fmaxf(v.w + b1, 0.f);
            }
            if (EPI == 2) {
                float2 r0 = *(const float2*)&pp.R[(size_t)row0 * N + col];
                float2 r1 = *(const float2*)&pp.R[(size_t)(row0 + 8) * N + col];
                v.x += r0.x; v.y += r0.y; v.z += r1.x; v.w += r1.y;
            }
            *(float2*)&pp.C[(size_t)row0 * N + col] = make_float2(v.x, v.y);
            *(float2*)&pp.C[(size_t)(row0 + 8) * N + col] = make_float2(v.z, v.w);
        }
    }
}

// ---------------- start head ----------------
__global__ void slog_k(const float* __restrict__ Rr, const float* __restrict__ w,
                       const float* __restrict__ b, float* __restrict__ slog) {
    int row  = blockIdx.x * 8 + (threadIdx.x >> 5);
    int lane = threadIdx.x & 31;
    const float* r = Rr + (size_t)row * Hh;
    float p = 0.f;
#pragma unroll
    for (int q = 0; q < 8; q++) p += r[lane + 32 * q] * w[lane + 32 * q];
    p = warp_sum(p);
    if (lane == 0) slog[row] = p + b[0];
}

__global__ __launch_bounds__(1024) void lse4096_k(const float* __restrict__ x, float* __restrict__ out) {
    int tid = threadIdx.x;
    float m = -CUDART_INF_F, s = 0.f;
    for (int i = tid; i < Cc; i += 1024) lse_acc(m, s, x[i]);
#pragma unroll
    for (int o = 16; o > 0; o >>= 1) {
        float m2 = __shfl_xor_sync(0xffffffffu, m, o);
        float s2 = __shfl_xor_sync(0xffffffffu, s, o);
        lse_merge(m, s, m2, s2);
    }
    __shared__ float sm[32], ss[32];
    int w = tid >> 5, lane = tid & 31;
    if (lane == 0) { sm[w] = m; ss[w] = s; }
    __syncthreads();
    if (tid == 0) {
        float M = sm[0], S = ss[0];
        for (int i = 1; i < 32; i++) lse_merge(M, S, sm[i], ss[i]);
        out[0] = M + __logf(S);
    }
}

__global__ void translse_k(const float* __restrict__ X, float* __restrict__ out) {
    const float* x = X + (size_t)blockIdx.x * Cc;
    int tid = threadIdx.x;
    float m = -CUDART_INF_F, s = 0.f;
    for (int i = tid; i < Cc; i += 256) lse_acc(m, s, x[i]);
#pragma unroll
    for (int o = 16; o > 0; o >>= 1) {
        float m2 = __shfl_xor_sync(0xffffffffu, m, o);
        float s2 = __shfl_xor_sync(0xffffffffu, s, o);
        lse_merge(m, s, m2, s2);
    }
    __shared__ float sm[8], ss[8];
    int w = tid >> 5, lane = tid & 31;
    if (lane == 0) { sm[w] = m; ss[w] = s; }
    __syncthreads();
    if (tid == 0) {
        float M = sm[0], S = ss[0];
        for (int i = 1; i < 8; i++) lse_merge(M, S, sm[i], ss[i]);
        out[blockIdx.x] = M + __logf(S);
    }
}

__global__ void transpose_k(const float* __restrict__ in, float* __restrict__ out) {
    __shared__ float t[32][33];
    int bx = blockIdx.x * 32;
    int by = blockIdx.y * 32;
    int x = threadIdx.x, y = threadIdx.y;
#pragma unroll
    for (int i = 0; i < 32; i += 8)
        t[y + i][x] = in[(size_t)(by + y + i) * Vv + bx + x];
    __syncthreads();
#pragma unroll
    for (int i = 0; i < 32; i += 8)
        out[(size_t)(bx + y + i) * Hh + by + x] = t[x][y + i];
}

__global__ void initmax_k(int* __restrict__ rm, float* __restrict__ rs) {
    int i = blockIdx.x * 256 + threadIdx.x;
    if (i < Cc) { rm[i] = (int)0x80000000; rs[i] = 0.f; }
}

__global__ __launch_bounds__(256) void emlog_k(
    const float* __restrict__ pre, const float* __restrict__ ewT,
    const float* __restrict__ eb, const int* __restrict__ w2s,
    float* __restrict__ L, int* __restrict__ rowmax)
{
    int v = blockIdx.x;
    __shared__ float ecol[Hh];
    __shared__ int st[SPW];
    int tid = threadIdx.x;
    ecol[tid] = ewT[(size_t)v * Hh + tid];
    if (tid < SPW) st[tid] = w2s[v * SPW + tid];
    __syncthreads();
    int w = tid >> 5, lane = tid & 31;
    float bv = eb[v];
    for (int jj = w; jj < SPW; jj += 8) {
        int c = st[jj];
        const float* pr = pre + (size_t)c * Hh;
        float p = 0.f;
#pragma unroll
        for (int q = 0; q < 8; q++) p += pr[lane + 32 * q] * ecol[lane + 32 * q];
        p = warp_sum(p);
        if (lane == 0) {
            float val = p + bv;
            L[v * SPW + jj] = val;
            atomicMax(&rowmax[c], ford(val));
        }
    }
}

__global__ void rmdec_k(const int* __restrict__ rm, float* __restrict__ rmf) {
    int i = blockIdx.x * 256 + threadIdx.x;
    if (i < Cc) rmf[i] = deord(rm[i]);
}

__global__ void emsum_k(const int* __restrict__ w2s, const float* __restrict__ L,
                        const float* __restrict__ rmf, float* __restrict__ rsum) {
    int gid = blockIdx.x * 256 + threadIdx.x;
    int v = gid >> 5, j = gid & 31;
    int c = w2s[v * SPW + j];
    for (int jp = 0; jp < j; jp++)
        if (w2s[v * SPW + jp] == c) return;
    atomicAdd(&rsum[c], __expf(L[gid] - rmf[c]));
}

__global__ void stlse_k(const float* __restrict__ rmf, const float* __restrict__ rsum,
                        float* __restrict__ stlse) {
    int i = blockIdx.x * 256 + threadIdx.x;
    if (i < Cc) stlse[i] = rmf[i] + __logf(rsum[i]);
}

__global__ void obs_k(const int* __restrict__ text, const int* __restrict__ w2s,
                      const float* __restrict__ L, const float* __restrict__ stlse,
                      const float* __restrict__ slog, const float* __restrict__ slse,
                      float* __restrict__ obs, float* __restrict__ initb) {
    int gid = blockIdx.x * 256 + threadIdx.x;
    int tok = gid >> 5, j = gid & 31;
    int v = text[tok];
    int c = w2s[v * SPW + j];
    obs[gid] = L[v * SPW + j] - stlse[c];
    if ((tok & (Tt - 1)) == 0)
        initb[(tok >> 7) * SPW + j] = slog[c] - slse[0];
}

__global__ __launch_bounds__(1024) void phi_k(
    const int* __restrict__ text, const int* __restrict__ w2s,
    const float* __restrict__ trans, const float* __restrict__ tlse,
    const float* __restrict__ obs, const float* __restrict__ initb,
    float* __restrict__ phi)
{
    int b = blockIdx.x;
    int n = b / Tm1, t = b % Tm1;
    __shared__ int c0[SPW], c1[SPW];
    __shared__ float ob1[SPW], iob[SPW];
    int tid = threadIdx.x;
    if (tid < SPW) {
        int v0 = text[n * Tt + t], v1 = text[n * Tt + t + 1];
        c0[tid] = w2s[v0 * SPW + tid];
        c1[tid] = w2s[v1 * SPW + tid];
        ob1[tid] = obs[(size_t)(n * Tt + t + 1) * SPW + tid];
        iob[tid] = (t == 0) ? (initb[n * SPW + tid] + obs[(size_t)(n * Tt) * SPW + tid]) : 0.f;
    }
    __syncthreads();
    int k = tid >> 5, j = tid & 31;
    float val = trans[(size_t)c0[j] * Cc + c1[k]] - tlse[c0[j]] + ob1[k] + iob[j];
    phi[(size_t)(t * Nn + n) * 1024 + tid] = val;
}

__global__ __launch_bounds__(1024) void scan_k(
    const float* __restrict__ phi, float* __restrict__ ap, float* __restrict__ bn,
    float* __restrict__ logZ, float* __restrict__ out)
{
    __shared__ float a_s[SPW];
    __shared__ float tile[SPW * 33];
    int tid = threadIdx.x, w = tid >> 5, lane = tid & 31;
    bool bwd = blockIdx.x >= Nn;
    int n = bwd ? (int)blockIdx.x - Nn : (int)blockIdx.x;
    if (tid < SPW) a_s[tid] = 0.f;
    __syncthreads();
    if (!bwd) {
        float pv = phi[(size_t)n * 1024 + tid];
        for (int t = 0; t < Tm1; t++) {
            float pvn = (t + 1 < Tm1) ? phi[(size_t)((t + 1) * Nn + n) * 1024 + tid] : 0.f;
            if (tid < SPW) ap[(size_t)(t * Nn + n) * SPW + tid] = a_s[tid];
            float x = pv + a_s[lane];
            float m = warp_max(x);
            float s = warp_sum(__expf(x - m));
            float nv = m + __logf(s);
            __syncthreads();
            if (lane == 0) a_s[w] = nv;
            __syncthreads();
            pv = pvn;
        }
        if (w == 0) {
            float x = a_s[lane];
            float m = warp_max(x);
            float s = warp_sum(__expf(x - m));
            float lz = m + __logf(s);
            if (lane == 0) logZ[n] = lz;
            out[2 + n * SPW + lane] = x - lz;
        }
    } else {
        float pv = phi[(size_t)((Tm1 - 1) * Nn + n) * 1024 + tid];
        for (int t = Tm1 - 1; t >= 0; t--) {
            float pvn = (t > 0) ? phi[(size_t)((t - 1) * Nn + n) * 1024 + tid] : 0.f;
            tile[w * 33 + lane] = pv;
            if (tid < SPW) bn[(size_t)(t * Nn + n) * SPW + tid] = a_s[tid];
            __syncthreads();
            float x = tile[lane * 33 + w] + a_s[lane];
            float m = warp_max(x);
            float s = warp_sum(__expf(x - m));
            float nv = m + __logf(s);
            __syncthreads();
            if (lane == 0) a_s[w] = nv;
            __syncthreads();
            pv = pvn;
        }
    }
}

__global__ void evid_k(const float* __restrict__ logZ, float* __restrict__ out) {
    if (threadIdx.x == 0) {
        float s = 0.f;
        for (int i = 0; i < Nn; i++) s += logZ[i];
        out[1] = s;
        out[0] = 0.f;
    }
}

__global__ __launch_bounds__(1024) void elbo_k(
    const float* __restrict__ phi, const float* __restrict__ ap,
    const float* __restrict__ bn, const float* __restrict__ logZ,
    float* __restrict__ out)
{
    int e = blockIdx.x;
    int n = e % Nn;
    __shared__ float sap[SPW], sbn[SPW], ws[32];
    int tid = threadIdx.x;
    if (tid < SPW) { sap[tid] = ap[(size_t)e * SPW + tid]; sbn[tid] = bn[(size_t)e * SPW + tid]; }
    __syncthreads();
    int k = tid >> 5, j = tid & 31;
    float p = phi[(size_t)e * 1024 + tid];
    float term = __expf(sap[j] + p + sbn[k] - logZ[n]) * p;
    term = warp_sum(term);
    if (j == 0) ws[k] = term;
    __syncthreads();
    if (tid < 32) {
        float v = warp_sum(ws[tid]);
        if (tid == 0) atomicAdd(&out[0], v);
    }
}

// ---------------- launcher ----------------
extern "C" void kernel_launch(void* const* d_in, const int* in_sizes, int n_in,
                              void* d_out, int out_size) {
    const float* start_emb = (const float*)d_in[0];
    const float* sw1  = (const float*)d_in[1];
    const float* sb1  = (const float*)d_in[2];
    const float* sw2  = (const float*)d_in[3];
    const float* sb2  = (const float*)d_in[4];
    const float* s_out_w = (const float*)d_in[5];
    const float* s_out_b = (const float*)d_in[6];
    const float* state_emb = (const float*)d_in[7];
    const float* tw1  = (const float*)d_in[8];
    const float* tb1  = (const float*)d_in[9];
    const float* tw2  = (const float*)d_in[10];
    const float* tb2  = (const float*)d_in[11];
    const float* nsp  = (const float*)d_in[12];
    const float* pre_emb = (const float*)d_in[13];
    const float* ew1  = (const float*)d_in[14];
    const float* eb1  = (const float*)d_in[15];
    const float* ew2  = (const float*)d_in[16];
    const float* eb2  = (const float*)d_in[17];
    const float* e_out_w = (const float*)d_in[18];
    const float* e_out_b = (const float*)d_in[19];
    const int* text = (const int*)d_in[20];
    const int* w2s  = (const int*)d_in[21];
    float* out = (float*)d_out;

    float* S = nullptr; int* RM = nullptr;
    cudaGetSymbolAddress((void**)&S, g_scr);
    cudaGetSymbolAddress((void**)&RM, g_rowmax);

    initmax_k<<<16, 256>>>(RM, S + OFF_RSUM);

    // batched MLP layer 1 (3 chains in one launch)
    Batch b1;
    b1.p[0] = { start_emb, sw1, sb1, nullptr, S + OFF_H0 };
    b1.p[1] = { state_emb, tw1, tb1, nullptr, S + OFF_H1 };
    b1.p[2] = { pre_emb,   ew1, eb1, nullptr, S + OFF_H2 };
    gemm_tc<1, false><<<dim3(Hh / 64, Cc / 128, 3), 256>>>(b1, Cc, Hh, Hh);

    // batched MLP layer 2 (relu + residual)
    Batch b2;
    b2.p[0] = { S + OFF_H0, sw2, sb2, start_emb, S + OFF_RS };
    b2.p[1] = { S + OFF_H1, tw2, tb2, state_emb, S + OFF_RST };
    b2.p[2] = { S + OFF_H2, ew2, eb2, pre_emb,   S + OFF_RP };
    gemm_tc<2, false><<<dim3(Hh / 64, Cc / 128, 3), 256>>>(b2, Cc, Hh, Hh);

    // start distribution
    slog_k<<<Cc / 8, 256>>>(S + OFF_RS, s_out_w, s_out_b, S + OFF_SLOG);
    lse4096_k<<<1, 1024>>>(S + OFF_SLOG, S + OFF_SLSE);

    // transition logits (RST @ nsp^T) + row lse
    Batch bt;
    bt.p[0] = { S + OFF_RST, nsp, nullptr, nullptr, S + OFF_TRANS };
    bt.p[1] = bt.p[0]; bt.p[2] = bt.p[0];
    gemm_tc<0, true><<<dim3(Cc / 64, Cc / 128, 1), 256>>>(bt, Cc, Cc, Hh);
    translse_k<<<Cc, 256>>>(S + OFF_TRANS, S + OFF_TLSE);

    // sparse emission
    transpose_k<<<dim3(Vv / 32, Hh / 32), dim3(32, 8)>>>(e_out_w, S + OFF_EWT);
    emlog_k<<<Vv, 256>>>(S + OFF_RP, S + OFF_EWT, e_out_b, w2s, S + OFF_L, RM);
    rmdec_k<<<16, 256>>>(RM, S + OFF_RMF);
    emsum_k<<<Vv * SPW / 256, 256>>>(w2s, S + OFF_L, S + OFF_RMF, S + OFF_RSUM);
    stlse_k<<<16, 256>>>(S + OFF_RMF, S + OFF_RSUM, S + OFF_STLSE);

    // obs/init, phi, scans, reductions
    obs_k<<<Nn * Tt * SPW / 256, 256>>>(text, w2s, S + OFF_L, S + OFF_STLSE,
                                        S + OFF_SLOG, S + OFF_SLSE, S + OFF_OBS, S + OFF_INIT);
    phi_k<<<Nn * Tm1, 1024>>>(text, w2s, S + OFF_TRANS, S + OFF_TLSE,
                              S + OFF_OBS, S + OFF_INIT, S + OFF_PHI);
    scan_k<<<2 * Nn, 1024>>>(S + OFF_PHI, S + OFF_AP, S + OFF_BN, S + OFF_LOGZ, out);
    evid_k<<<1, 32>>>(S + OFF_LOGZ, out);
    elbo_k<<<Tm1 * Nn, 1024>>>(S + OFF_PHI, S + OFF_AP, S + OFF_BN, S + OFF_LOGZ, out);
}

// round 3
// speedup vs baseline: 1.3724x; 1.0836x over previous
#include <cuda_runtime.h>
#include <math_constants.h>
#include <cstdint>
#include <cstddef>

static constexpr int Vv = 16000, Cc = 4096, Hh = 256, SPW = 32, Nn = 32, Tt = 128, Tm1 = 127;

// ---------------- scratch layout ----------------
constexpr size_t SZ_MAT   = (size_t)Cc * Hh;                  // 1,048,576
constexpr size_t OFF_H0   = 0;
constexpr size_t OFF_H1   = OFF_H0   + SZ_MAT;
constexpr size_t OFF_H2   = OFF_H1   + SZ_MAT;
constexpr size_t OFF_RS   = OFF_H2   + SZ_MAT;
constexpr size_t OFF_RST  = OFF_RS   + SZ_MAT;
constexpr size_t OFF_RP   = OFF_RST  + SZ_MAT;
constexpr size_t OFF_TRANS= OFF_RP   + SZ_MAT;                // 4096x4096
constexpr size_t OFF_TLSE = OFF_TRANS+ (size_t)Cc * Cc;
constexpr size_t OFF_SLOG = OFF_TLSE + Cc;
constexpr size_t OFF_SLSE = OFF_SLOG + Cc;
constexpr size_t OFF_EWT  = OFF_SLSE + 32;                    // V x H
constexpr size_t OFF_L    = OFF_EWT  + (size_t)Vv * Hh;       // V x SPW
constexpr size_t OFF_RSUM = OFF_L    + (size_t)Vv * SPW;
constexpr size_t OFF_STLSE= OFF_RSUM + Cc;
constexpr size_t OFF_OBS  = OFF_STLSE+ Cc;
constexpr size_t OFF_INIT = OFF_OBS  + (size_t)Nn * Tt * SPW;
constexpr size_t OFF_PHI  = OFF_INIT + (size_t)Nn * SPW;
constexpr size_t OFF_AP   = OFF_PHI  + (size_t)Tm1 * Nn * SPW * SPW;
constexpr size_t OFF_BN   = OFF_AP   + (size_t)Tm1 * Nn * SPW;
constexpr size_t OFF_LOGZ = OFF_BN   + (size_t)Tm1 * Nn * SPW;
constexpr size_t OFF_PART = OFF_LOGZ + 64;                    // 4096 x 128 x (m,s)
constexpr size_t SCRATCH_TOTAL = OFF_PART + (size_t)Cc * 128 * 2;

__device__ float g_scr[SCRATCH_TOTAL];
__device__ int   g_rowmax[Cc];
// tf32 hi/lo pre-split buffers: A(RST) hi/lo, B(nsp) hi/lo
__device__ uint32_t g_u[4 * SZ_MAT];
constexpr size_t UAH = 0, UAL = SZ_MAT, UBH = 2 * SZ_MAT, UBL = 3 * SZ_MAT;

// ---------------- helpers ----------------
__device__ __forceinline__ int ford(float f) {
    int i = __float_as_int(f);
    return i >= 0 ? i : (i ^ 0x7fffffff);
}
__device__ __forceinline__ float deord(int i) {
    return __int_as_float(i >= 0 ? i : (i ^ 0x7fffffff));
}
__device__ __forceinline__ void lse_acc(float& m, float& s, float v) {
    if (v > m) { s = s * __expf(m - v) + 1.f; m = v; }
    else       { s += __expf(v - m); }
}
__device__ __forceinline__ void lse_merge(float& m, float& s, float m2, float s2) {
    if (m2 > m) { s = s * __expf(m - m2) + s2; m = m2; }
    else        { s += s2 * __expf(m2 - m); }
}
__device__ __forceinline__ float warp_sum(float v) {
#pragma unroll
    for (int o = 16; o > 0; o >>= 1) v += __shfl_xor_sync(0xffffffffu, v, o);
    return v;
}
__device__ __forceinline__ float warp_max(float v) {
#pragma unroll
    for (int o = 16; o > 0; o >>= 1) v = fmaxf(v, __shfl_xor_sync(0xffffffffu, v, o));
    return v;
}

// ---------------- tf32 utils ----------------
__device__ __forceinline__ uint32_t f2tf(float x) {
    uint32_t r;
    asm("cvt.rna.tf32.f32 %0, %1;" : "=r"(r) : "f"(x));
    return r;
}
__device__ __forceinline__ void tf_split(float x, uint32_t& hi, uint32_t& lo) {
    hi = f2tf(x);
    lo = f2tf(x - __uint_as_float(hi));
}
__device__ __forceinline__ void mma_tf32(float4& d, const uint32_t* a, const uint32_t* b) {
    asm volatile(
        "mma.sync.aligned.m16n8k8.row.col.f32.tf32.tf32.f32 "
        "{%0,%1,%2,%3}, {%4,%5,%6,%7}, {%8,%9}, {%0,%1,%2,%3};"
        : "+f"(d.x), "+f"(d.y), "+f"(d.z), "+f"(d.w)
        : "r"(a[0]), "r"(a[1]), "r"(a[2]), "r"(a[3]), "r"(b[0]), "r"(b[1]));
}
__device__ __forceinline__ void cpasync16(uint32_t dst, const void* src) {
    asm volatile("cp.async.cg.shared.global [%0], [%1], 16;" :: "r"(dst), "l"(src));
}
__device__ __forceinline__ void cp_commit() { asm volatile("cp.async.commit_group;"); }
template <int N> __device__ __forceinline__ void cp_wait() {
    asm volatile("cp.async.wait_group %0;" :: "n"(N));
}

// split fp32 matrix into tf32 hi/lo (vectorized, 4 elems/thread)
__global__ void presplit_k(const float* __restrict__ in, uint32_t* __restrict__ hi,
                           uint32_t* __restrict__ lo) {
    int i = blockIdx.x * blockDim.x + threadIdx.x;
    float4 v = ((const float4*)in)[i];
    uint4 h, l;
    tf_split(v.x, h.x, l.x); tf_split(v.y, h.y, l.y);
    tf_split(v.z, h.z, l.z); tf_split(v.w, h.w, l.w);
    ((uint4*)hi)[i] = h; ((uint4*)lo)[i] = l;
}

// ---------------- MLP GEMM (round-2 style, batched z=3) ----------------
struct P3 { const float* A; const float* B; const float* bias; const float* R; float* C; };
struct Batch { P3 p[3]; };

template <int EPI>
__global__ __launch_bounds__(256, 2) void gemm_tc(Batch bt, int M, int N, int K) {
    constexpr int BM = 128, BN = 64, BK = 16;
    __shared__ uint32_t Ah[BK][BM + 8], Al[BK][BM + 8];
    __shared__ uint32_t Bh[BK][BN + 8], Bl[BK][BN + 8];
    const P3 pp = bt.p[blockIdx.z];
    int tid = threadIdx.x;
    int bm = blockIdx.y * BM, bn = blockIdx.x * BN;
    int wid = tid >> 5, lane = tid & 31;
    int gid = lane >> 2, tg = lane & 3;
    int warp_m = (wid & 3) * 32, warp_n = (wid >> 2) * 32;

    float4 acc[2][4];
#pragma unroll
    for (int i = 0; i < 2; i++)
#pragma unroll
        for (int j = 0; j < 4; j++) acc[i][j] = make_float4(0.f, 0.f, 0.f, 0.f);

    for (int k0 = 0; k0 < K; k0 += BK) {
#pragma unroll
        for (int i = 0; i < 2; i++) {
            int f = tid + i * 256;
            int r = f >> 2, c4 = (f & 3) * 4;
            float4 v = *(const float4*)&pp.A[(size_t)(bm + r) * K + k0 + c4];
            tf_split(v.x, Ah[c4 + 0][r], Al[c4 + 0][r]);
            tf_split(v.y, Ah[c4 + 1][r], Al[c4 + 1][r]);
            tf_split(v.z, Ah[c4 + 2][r], Al[c4 + 2][r]);
            tf_split(v.w, Ah[c4 + 3][r], Al[c4 + 3][r]);
        }
        {
            int r = tid >> 4, c = (tid & 15) * 4;      // r = k, c = n
            float4 v = *(const float4*)&pp.B[(size_t)(k0 + r) * N + bn + c];
            tf_split(v.x, Bh[r][c + 0], Bl[r][c + 0]);
            tf_split(v.y, Bh[r][c + 1], Bl[r][c + 1]);
            tf_split(v.z, Bh[r][c + 2], Bl[r][c + 2]);
            tf_split(v.w, Bh[r][c + 3], Bl[r][c + 3]);
        }
        __syncthreads();
#pragma unroll
        for (int kk = 0; kk < BK; kk += 8) {
            uint32_t ah[2][4], al[2][4], bh[4][2], bl[4][2];
#pragma unroll
            for (int mt = 0; mt < 2; mt++) {
                int rb = warp_m + mt * 16 + gid;
                ah[mt][0] = Ah[kk + tg][rb];     al[mt][0] = Al[kk + tg][rb];
                ah[mt][1] = Ah[kk + tg][rb + 8]; al[mt][1] = Al[kk + tg][rb + 8];
                ah[mt][2] = Ah[kk + tg + 4][rb];     al[mt][2] = Al[kk + tg + 4][rb];
                ah[mt][3] = Ah[kk + tg + 4][rb + 8]; al[mt][3] = Al[kk + tg + 4][rb + 8];
            }
#pragma unroll
            for (int nt = 0; nt < 4; nt++) {
                int cb = warp_n + nt * 8 + gid;
                bh[nt][0] = Bh[kk + tg][cb];     bl[nt][0] = Bl[kk + tg][cb];
                bh[nt][1] = Bh[kk + tg + 4][cb]; bl[nt][1] = Bl[kk + tg + 4][cb];
            }
#pragma unroll
            for (int mt = 0; mt < 2; mt++)
#pragma unroll
                for (int nt = 0; nt < 4; nt++) {
                    mma_tf32(acc[mt][nt], ah[mt], bh[nt]);
                    mma_tf32(acc[mt][nt], al[mt], bh[nt]);
                    mma_tf32(acc[mt][nt], ah[mt], bl[nt]);
                }
        }
        __syncthreads();
    }

#pragma unroll
    for (int mt = 0; mt < 2; mt++) {
        int row0 = bm + warp_m + mt * 16 + gid;
#pragma unroll
        for (int nt = 0; nt < 4; nt++) {
            int col = bn + warp_n + nt * 8 + 2 * tg;
            float4 v = acc[mt][nt];
            if (EPI >= 1) {
                float b0 = pp.bias[col], b1 = pp.bias[col + 1];
                v.x = fmaxf(v.x + b0, 0.f); v.y = fmaxf(v.y + b1, 0.f);
                v.z = fmaxf(v.z + b0, 0.f); v.w = fmaxf(v.w + b1, 0.f);
            }
            if (EPI == 2) {
                float2 r0 = *(const float2*)&pp.R[(size_t)row0 * N + col];
                float2 r1 = *(const float2*)&pp.R[(size_t)(row0 + 8) * N + col];
                v.x += r0.x; v.y += r0.y; v.z += r1.x; v.w += r1.y;
            }
            *(float2*)&pp.C[(size_t)row0 * N + col] = make_float2(v.x, v.y);
            *(float2*)&pp.C[(size_t)(row0 + 8) * N + col] = make_float2(v.z, v.w);
        }
    }
}

// ---------------- trans GEMM: pre-split hi/lo inputs, cp.async pipeline, fused lse partials --
// C[4096,4096] = A[4096,256] @ B[4096,256]^T, 3xTF32
__global__ __launch_bounds__(256) void gemm2_tc(
    const uint32_t* __restrict__ Ahg, const uint32_t* __restrict__ Alg,
    const uint32_t* __restrict__ Bhg, const uint32_t* __restrict__ Blg,
    float* __restrict__ C, float2* __restrict__ part)
{
    constexpr int K = 256, NIT = K / 8, BUF = 4608;  // per-buf u32: Ah(128*12) Al Bh(64*12) Bl
    __shared__ uint32_t smem[2 * BUF];
    int tid = threadIdx.x, wid = tid >> 5, lane = tid & 31;
    int gid = lane >> 2, tg = lane & 3;
    int bm = blockIdx.y * 128, bn = blockIdx.x * 64;
    int warp_m = (wid & 3) * 32, warp_n = (wid >> 2) * 32;

    // per-thread cp.async chunks (3 x 16B per stage)
    const uint32_t* gsrc[3]; uint32_t doff[3];
#pragma unroll
    for (int i = 0; i < 3; i++) {
        int ch = tid + i * 256;
        if (ch < 512) {
            int mat = ch >> 8, r = (ch >> 1) & 127, c4 = (ch & 1) * 4;
            gsrc[i] = (mat ? Alg : Ahg) + (size_t)(bm + r) * K + c4;
            doff[i] = mat * 1536 + r * 12 + c4;
        } else {
            int idx = ch - 512;
            int mat = idx >> 7, r = (idx >> 1) & 63, c4 = (idx & 1) * 4;
            gsrc[i] = (mat ? Blg : Bhg) + (size_t)(bn + r) * K + c4;
            doff[i] = 3072 + mat * 768 + r * 12 + c4;
        }
    }
    uint32_t sbase = (uint32_t)__cvta_generic_to_shared(smem);

    float4 acc[2][4];
#pragma unroll
    for (int i = 0; i < 2; i++)
#pragma unroll
        for (int j = 0; j < 4; j++) acc[i][j] = make_float4(0.f, 0.f, 0.f, 0.f);

    // prologue
    {
        uint32_t b = sbase;
#pragma unroll
        for (int i = 0; i < 3; i++) cpasync16(b + doff[i] * 4, gsrc[i]);
        cp_commit();
    }
    for (int it = 0; it < NIT; it++) {
        if (it + 1 < NIT) {
            uint32_t b = sbase + ((it + 1) & 1) * (BUF * 4);
#pragma unroll
            for (int i = 0; i < 3; i++) cpasync16(b + doff[i] * 4, gsrc[i] + (it + 1) * 8);
            cp_commit();
            cp_wait<1>();
        } else {
            cp_wait<0>();
        }
        __syncthreads();
        const uint32_t* buf = smem + (it & 1) * BUF;
        uint32_t ah[2][4], al[2][4], bh[4][2], bl[4][2];
#pragma unroll
        for (int mt = 0; mt < 2; mt++) {
            int rb = warp_m + mt * 16 + gid;
            ah[mt][0] = buf[rb * 12 + tg];           al[mt][0] = buf[1536 + rb * 12 + tg];
            ah[mt][1] = buf[(rb + 8) * 12 + tg];     al[mt][1] = buf[1536 + (rb + 8) * 12 + tg];
            ah[mt][2] = buf[rb * 12 + tg + 4];       al[mt][2] = buf[1536 + rb * 12 + tg + 4];
            ah[mt][3] = buf[(rb + 8) * 12 + tg + 4]; al[mt][3] = buf[1536 + (rb + 8) * 12 + tg + 4];
        }
#pragma unroll
        for (int nt = 0; nt < 4; nt++) {
            int cb = warp_n + nt * 8 + gid;
            bh[nt][0] = buf[3072 + cb * 12 + tg];     bl[nt][0] = buf[3840 + cb * 12 + tg];
            bh[nt][1] = buf[3072 + cb * 12 + tg + 4]; bl[nt][1] = buf[3840 + cb * 12 + tg + 4];
        }
#pragma unroll
        for (int mt = 0; mt < 2; mt++)
#pragma unroll
            for (int nt = 0; nt < 4; nt++) {
                mma_tf32(acc[mt][nt], ah[mt], bh[nt]);
                mma_tf32(acc[mt][nt], al[mt], bh[nt]);
                mma_tf32(acc[mt][nt], ah[mt], bl[nt]);
            }
        __syncthreads();
    }

    // epilogue: store C + per-row (m,s) partials over this warp's 32 cols
    int chunk = blockIdx.x * 2 + (wid >> 2);
#pragma unroll
    for (int mt = 0; mt < 2; mt++) {
        int row0 = bm + warp_m + mt * 16 + gid;
        float m0 = -CUDART_INF_F, s0 = 0.f, m8 = -CUDART_INF_F, s8 = 0.f;
#pragma unroll
        for (int nt = 0; nt < 4; nt++) {
            int col = bn + warp_n + nt * 8 + 2 * tg;
            float4 v = acc[mt][nt];
            *(float2*)&C[(size_t)row0 * Cc + col] = make_float2(v.x, v.y);
            *(float2*)&C[(size_t)(row0 + 8) * Cc + col] = make_float2(v.z, v.w);
            lse_acc(m0, s0, v.x); lse_acc(m0, s0, v.y);
            lse_acc(m8, s8, v.z); lse_acc(m8, s8, v.w);
        }
#pragma unroll
        for (int o = 1; o <= 2; o <<= 1) {
            float m2 = __shfl_xor_sync(0xffffffffu, m0, o);
            float s2 = __shfl_xor_sync(0xffffffffu, s0, o);
            lse_merge(m0, s0, m2, s2);
            m2 = __shfl_xor_sync(0xffffffffu, m8, o);
            s2 = __shfl_xor_sync(0xffffffffu, s8, o);
            lse_merge(m8, s8, m2, s2);
        }
        if (tg == 0) {
            part[(size_t)row0 * 128 + chunk] = make_float2(m0, s0);
            part[(size_t)(row0 + 8) * 128 + chunk] = make_float2(m8, s8);
        }
    }
}

// merge 128 (m,s) partials per row -> tlse
__global__ void tlsemerge_k(const float2* __restrict__ part, float* __restrict__ tlse) {
    int row = blockIdx.x * 8 + (threadIdx.x >> 5);
    int lane = threadIdx.x & 31;
    float m = -CUDART_INF_F, s = 0.f;
#pragma unroll
    for (int i = 0; i < 4; i++) {
        float2 p = part[(size_t)row * 128 + lane + 32 * i];
        lse_merge(m, s, p.x, p.y);
    }
#pragma unroll
    for (int o = 16; o > 0; o >>= 1) {
        float m2 = __shfl_xor_sync(0xffffffffu, m, o);
        float s2 = __shfl_xor_sync(0xffffffffu, s, o);
        lse_merge(m, s, m2, s2);
    }
    if (lane == 0) tlse[row] = m + __logf(s);
}

// ---------------- start head ----------------
__global__ void slog_k(const float* __restrict__ Rr, const float* __restrict__ w,
                       const float* __restrict__ b, float* __restrict__ slog) {
    int row  = blockIdx.x * 8 + (threadIdx.x >> 5);
    int lane = threadIdx.x & 31;
    const float* r = Rr + (size_t)row * Hh;
    float p = 0.f;
#pragma unroll
    for (int q = 0; q < 8; q++) p += r[lane + 32 * q] * w[lane + 32 * q];
    p = warp_sum(p);
    if (lane == 0) slog[row] = p + b[0];
}

__global__ __launch_bounds__(1024) void lse4096_k(const float* __restrict__ x, float* __restrict__ out) {
    int tid = threadIdx.x;
    float m = -CUDART_INF_F, s = 0.f;
    for (int i = tid; i < Cc; i += 1024) lse_acc(m, s, x[i]);
#pragma unroll
    for (int o = 16; o > 0; o >>= 1) {
        float m2 = __shfl_xor_sync(0xffffffffu, m, o);
        float s2 = __shfl_xor_sync(0xffffffffu, s, o);
        lse_merge(m, s, m2, s2);
    }
    __shared__ float sm[32], ss[32];
    int w = tid >> 5, lane = tid & 31;
    if (lane == 0) { sm[w] = m; ss[w] = s; }
    __syncthreads();
    if (tid == 0) {
        float M = sm[0], S = ss[0];
        for (int i = 1; i < 32; i++) lse_merge(M, S, sm[i], ss[i]);
        out[0] = M + __logf(S);
    }
}

__global__ void transpose_k(const float* __restrict__ in, float* __restrict__ out) {
    __shared__ float t[32][33];
    int bx = blockIdx.x * 32;
    int by = blockIdx.y * 32;
    int x = threadIdx.x, y = threadIdx.y;
#pragma unroll
    for (int i = 0; i < 32; i += 8)
        t[y + i][x] = in[(size_t)(by + y + i) * Vv + bx + x];
    __syncthreads();
#pragma unroll
    for (int i = 0; i < 32; i += 8)
        out[(size_t)(bx + y + i) * Hh + by + x] = t[x][y + i];
}

__global__ void initmax_k(int* __restrict__ rm, float* __restrict__ rs) {
    int i = blockIdx.x * 256 + threadIdx.x;
    if (i < Cc) { rm[i] = (int)0x80000000; rs[i] = 0.f; }
}

__global__ __launch_bounds__(256) void emlog_k(
    const float* __restrict__ pre, const float* __restrict__ ewT,
    const float* __restrict__ eb, const int* __restrict__ w2s,
    float* __restrict__ L, int* __restrict__ rowmax)
{
    int v = blockIdx.x;
    __shared__ float ecol[Hh];
    __shared__ int st[SPW];
    int tid = threadIdx.x;
    ecol[tid] = ewT[(size_t)v * Hh + tid];
    if (tid < SPW) st[tid] = w2s[v * SPW + tid];
    __syncthreads();
    int w = tid >> 5, lane = tid & 31;
    float bv = eb[v];
    for (int jj = w; jj < SPW; jj += 8) {
        int c = st[jj];
        const float* pr = pre + (size_t)c * Hh;
        float p = 0.f;
#pragma unroll
        for (int q = 0; q < 8; q++) p += pr[lane + 32 * q] * ecol[lane + 32 * q];
        p = warp_sum(p);
        if (lane == 0) {
            float val = p + bv;
            L[v * SPW + jj] = val;
            atomicMax(&rowmax[c], ford(val));
        }
    }
}

__global__ void emsum_k(const int* __restrict__ w2s, const float* __restrict__ L,
                        const int* __restrict__ rm, float* __restrict__ rsum) {
    int gid = blockIdx.x * 256 + threadIdx.x;
    int v = gid >> 5, j = gid & 31;
    int c = w2s[v * SPW + j];
    for (int jp = 0; jp < j; jp++)
        if (w2s[v * SPW + jp] == c) return;
    atomicAdd(&rsum[c], __expf(L[gid] - deord(rm[c])));
}

__global__ void stlse_k(const int* __restrict__ rm, const float* __restrict__ rsum,
                        float* __restrict__ stlse) {
    int i = blockIdx.x * 256 + threadIdx.x;
    if (i < Cc) stlse[i] = deord(rm[i]) + __logf(rsum[i]);
}

__global__ void obs_k(const int* __restrict__ text, const int* __restrict__ w2s,
                      const float* __restrict__ L, const float* __restrict__ stlse,
                      const float* __restrict__ slog, const float* __restrict__ slse,
                      float* __restrict__ obs, float* __restrict__ initb) {
    int gid = blockIdx.x * 256 + threadIdx.x;
    int tok = gid >> 5, j = gid & 31;
    int v = text[tok];
    int c = w2s[v * SPW + j];
    obs[gid] = L[v * SPW + j] - stlse[c];
    if ((tok & (Tt - 1)) == 0)
        initb[(tok >> 7) * SPW + j] = slog[c] - slse[0];
}

__global__ __launch_bounds__(1024) void phi_k(
    const int* __restrict__ text, const int* __restrict__ w2s,
    const float* __restrict__ trans, const float* __restrict__ tlse,
    const float* __restrict__ obs, const float* __restrict__ initb,
    float* __restrict__ phi)
{
    int b = blockIdx.x;
    int n = b / Tm1, t = b % Tm1;
    __shared__ int c0[SPW], c1[SPW];
    __shared__ float ob1[SPW], iob[SPW];
    int tid = threadIdx.x;
    if (tid < SPW) {
        int v0 = text[n * Tt + t], v1 = text[n * Tt + t + 1];
        c0[tid] = w2s[v0 * SPW + tid];
        c1[tid] = w2s[v1 * SPW + tid];
        ob1[tid] = obs[(size_t)(n * Tt + t + 1) * SPW + tid];
        iob[tid] = (t == 0) ? (initb[n * SPW + tid] + obs[(size_t)(n * Tt) * SPW + tid]) : 0.f;
    }
    __syncthreads();
    int k = tid >> 5, j = tid & 31;
    float val = trans[(size_t)c0[j] * Cc + c1[k]] - tlse[c0[j]] + ob1[k] + iob[j];
    phi[(size_t)(t * Nn + n) * 1024 + tid] = val;
}

__global__ __launch_bounds__(1024) void scan_k(
    const float* __restrict__ phi, float* __restrict__ ap, float* __restrict__ bn,
    float* __restrict__ logZ, float* __restrict__ out)
{
    __shared__ float a_s[SPW];
    __shared__ float tile[SPW * 33];
    int tid = threadIdx.x, w = tid >> 5, lane = tid & 31;
    bool bwd = blockIdx.x >= Nn;
    int n = bwd ? (int)blockIdx.x - Nn : (int)blockIdx.x;
    if (tid < SPW) a_s[tid] = 0.f;
    __syncthreads();
    if (!bwd) {
        float pv = phi[(size_t)n * 1024 + tid];
        for (int t = 0; t < Tm1; t++) {
            float pvn = (t + 1 < Tm1) ? phi[(size_t)((t + 1) * Nn + n) * 1024 + tid] : 0.f;
            if (tid < SPW) ap[(size_t)(t * Nn + n) * SPW + tid] = a_s[tid];
            float x = pv + a_s[lane];
            float m = warp_max(x);
            float s = warp_sum(__expf(x - m));
            float nv = m + __logf(s);
            __syncthreads();
            if (lane == 0) a_s[w] = nv;
            __syncthreads();
            pv = pvn;
        }
        if (w == 0) {
            float x = a_s[lane];
            float m = warp_max(x);
            float s = warp_sum(__expf(x - m));
            float lz = m + __logf(s);
            if (lane == 0) logZ[n] = lz;
            out[2 + n * SPW + lane] = x - lz;
        }
    } else {
        float pv = phi[(size_t)((Tm1 - 1) * Nn + n) * 1024 + tid];
        for (int t = Tm1 - 1; t >= 0; t--) {
            float pvn = (t > 0) ? phi[(size_t)((t - 1) * Nn + n) * 1024 + tid] : 0.f;
            tile[w * 33 + lane] = pv;
            if (tid < SPW) bn[(size_t)(t * Nn + n) * SPW + tid] = a_s[tid];
            __syncthreads();
            float x = tile[lane * 33 + w] + a_s[lane];
            float m = warp_max(x);
            float s = warp_sum(__expf(x - m));
            float nv = m + __logf(s);
            __syncthreads();
            if (lane == 0) a_s[w] = nv;
            __syncthreads();
            pv = pvn;
        }
    }
}

__global__ void evid_k(const float* __restrict__ logZ, float* __restrict__ out) {
    if (threadIdx.x == 0) {
        float s = 0.f;
        for (int i = 0; i < Nn; i++) s += logZ[i];
        out[1] = s;
        out[0] = 0.f;
    }
}

__global__ __launch_bounds__(1024) void elbo_k(
    const float* __restrict__ phi, const float* __restrict__ ap,
    const float* __restrict__ bn, const float* __restrict__ logZ,
    float* __restrict__ out)
{
    int e = blockIdx.x;
    int n = e % Nn;
    __shared__ float sap[SPW], sbn[SPW], ws[32];
    int tid = threadIdx.x;
    if (tid < SPW) { sap[tid] = ap[(size_t)e * SPW + tid]; sbn[tid] = bn[(size_t)e * SPW + tid]; }
    __syncthreads();
    int k = tid >> 5, j = tid & 31;
    float p = phi[(size_t)e * 1024 + tid];
    float term = __expf(sap[j] + p + sbn[k] - logZ[n]) * p;
    term = warp_sum(term);
    if (j == 0) ws[k] = term;
    __syncthreads();
    if (tid < 32) {
        float v = warp_sum(ws[tid]);
        if (tid == 0) atomicAdd(&out[0], v);
    }
}

// ---------------- launcher ----------------
extern "C" void kernel_launch(void* const* d_in, const int* in_sizes, int n_in,
                              void* d_out, int out_size) {
    const float* start_emb = (const float*)d_in[0];
    const float* sw1  = (const float*)d_in[1];
    const float* sb1  = (const float*)d_in[2];
    const float* sw2  = (const float*)d_in[3];
    const float* sb2  = (const float*)d_in[4];
    const float* s_out_w = (const float*)d_in[5];
    const float* s_out_b = (const float*)d_in[6];
    const float* state_emb = (const float*)d_in[7];
    const float* tw1  = (const float*)d_in[8];
    const float* tb1  = (const float*)d_in[9];
    const float* tw2  = (const float*)d_in[10];
    const float* tb2  = (const float*)d_in[11];
    const float* nsp  = (const float*)d_in[12];
    const float* pre_emb = (const float*)d_in[13];
    const float* ew1  = (const float*)d_in[14];
    const float* eb1  = (const float*)d_in[15];
    const float* ew2  = (const float*)d_in[16];
    const float* eb2  = (const float*)d_in[17];
    const float* e_out_w = (const float*)d_in[18];
    const float* e_out_b = (const float*)d_in[19];
    const int* text = (const int*)d_in[20];
    const int* w2s  = (const int*)d_in[21];
    float* out = (float*)d_out;

    float* S = nullptr; int* RM = nullptr; uint32_t* U = nullptr;
    cudaGetSymbolAddress((void**)&S, g_scr);
    cudaGetSymbolAddress((void**)&RM, g_rowmax);
    cudaGetSymbolAddress((void**)&U, g_u);

    static bool inited = false;
    static cudaStream_t s1, s2;
    static cudaEvent_t evStart, evB2, evPS, evEm, evS;
    if (!inited) {
        cudaStreamCreateWithFlags(&s1, cudaStreamNonBlocking);
        cudaStreamCreateWithFlags(&s2, cudaStreamNonBlocking);
        cudaEventCreateWithFlags(&evStart, cudaEventDisableTiming);
        cudaEventCreateWithFlags(&evB2, cudaEventDisableTiming);
        cudaEventCreateWithFlags(&evPS, cudaEventDisableTiming);
        cudaEventCreateWithFlags(&evEm, cudaEventDisableTiming);
        cudaEventCreateWithFlags(&evS, cudaEventDisableTiming);
        inited = true;
    }

    cudaEventRecord(evStart, 0);
    cudaStreamWaitEvent(s1, evStart, 0);

    // ---- s1: input-only prep (concurrent with MLPs) ----
    initmax_k<<<16, 256, 0, s1>>>(RM, S + OFF_RSUM);
    transpose_k<<<dim3(Vv / 32, Hh / 32), dim3(32, 8), 0, s1>>>(e_out_w, S + OFF_EWT);
    presplit_k<<<SZ_MAT / 4 / 256, 256, 0, s1>>>(nsp, U + UBH, U + UBL);
    cudaEventRecord(evPS, s1);

    // ---- main: MLPs ----
    Batch b1;
    b1.p[0] = { start_emb, sw1, sb1, nullptr, S + OFF_H0 };
    b1.p[1] = { state_emb, tw1, tb1, nullptr, S + OFF_H1 };
    b1.p[2] = { pre_emb,   ew1, eb1, nullptr, S + OFF_H2 };
    gemm_tc<1><<<dim3(Hh / 64, Cc / 128, 3), 256>>>(b1, Cc, Hh, Hh);
    Batch b2;
    b2.p[0] = { S + OFF_H0, sw2, sb2, start_emb, S + OFF_RS };
    b2.p[1] = { S + OFF_H1, tw2, tb2, state_emb, S + OFF_RST };
    b2.p[2] = { S + OFF_H2, ew2, eb2, pre_emb,   S + OFF_RP };
    gemm_tc<2><<<dim3(Hh / 64, Cc / 128, 3), 256>>>(b2, Cc, Hh, Hh);
    cudaEventRecord(evB2, 0);

    // ---- s2: start head (concurrent with trans GEMM) ----
    cudaStreamWaitEvent(s2, evB2, 0);
    slog_k<<<Cc / 8, 256, 0, s2>>>(S + OFF_RS, s_out_w, s_out_b, S + OFF_SLOG);
    lse4096_k<<<1, 1024, 0, s2>>>(S + OFF_SLOG, S + OFF_SLSE);
    cudaEventRecord(evS, s2);

    // ---- s1: emission chain (concurrent with trans GEMM) ----
    cudaStreamWaitEvent(s1, evB2, 0);
    emlog_k<<<Vv, 256, 0, s1>>>(S + OFF_RP, S + OFF_EWT, e_out_b, w2s, S + OFF_L, RM);
    emsum_k<<<Vv * SPW / 256, 256, 0, s1>>>(w2s, S + OFF_L, RM, S + OFF_RSUM);
    stlse_k<<<16, 256, 0, s1>>>(RM, S + OFF_RSUM, S + OFF_STLSE);
    cudaEventRecord(evEm, s1);

    // ---- main: trans GEMM (pre-split + pipelined) + fused row-lse ----
    presplit_k<<<SZ_MAT / 4 / 256, 256>>>(S + OFF_RST, U + UAH, U + UAL);
    cudaStreamWaitEvent(0, evPS, 0);
    gemm2_tc<<<dim3(Cc / 64, Cc / 128), 256>>>(U + UAH, U + UAL, U + UBH, U + UBL,
                                               S + OFF_TRANS, (float2*)(S + OFF_PART));
    tlsemerge_k<<<Cc / 8, 256>>>((float2*)(S + OFF_PART), S + OFF_TLSE);

    // ---- join + tail ----
    cudaStreamWaitEvent(0, evEm, 0);
    cudaStreamWaitEvent(0, evS, 0);
    obs_k<<<Nn * Tt * SPW / 256, 256>>>(text, w2s, S + OFF_L, S + OFF_STLSE,
                                        S + OFF_SLOG, S + OFF_SLSE, S + OFF_OBS, S + OFF_INIT);
    phi_k<<<Nn * Tm1, 1024>>>(text, w2s, S + OFF_TRANS, S + OFF_TLSE,
                              S + OFF_OBS, S + OFF_INIT, S + OFF_PHI);
    scan_k<<<2 * Nn, 1024>>>(S + OFF_PHI, S + OFF_AP, S + OFF_BN, S + OFF_LOGZ, out);
    evid_k<<<1, 32>>>(S + OFF_LOGZ, out);
    elbo_k<<<Tm1 * Nn, 1024>>>(S + OFF_PHI, S + OFF_AP, S + OFF_BN, S + OFF_LOGZ, out);
}